// round 3
// baseline (speedup 1.0000x reference)
#include <cuda_runtime.h>
#include <cuda_bf16.h>
#include <cstdint>

// Problem constants (fixed by the reference setup_inputs)
#define B_  128
#define L_  2048
#define H_  768
#define H4_ 192          // H / 4 floats per float4
#define CHUNK_ROWS 64
#define NCHUNKS (L_ / CHUNK_ROWS)   // 32

// Clamped inclusive span [start, end] for batch b, span s (0=head,1=tail).
// JAX x64 is disabled by default -> entity_positions arrives as int32.
__device__ __forceinline__ void span_bounds(const int* __restrict__ pos,
                                            int b, int s, int& start, int& end) {
    int p0 = pos[b * 4 + s * 2];
    int p1 = pos[b * 4 + s * 2 + 1];
    int st = p0 < 0 ? 0 : (p0 > (L_ - 1) ? (L_ - 1) : p0);
    int en = p1 > (L_ - 1) ? (L_ - 1) : p1;
    if (en < st) en = st;
    start = st;
    end   = en;
}

// One block per (L-chunk, batch). Reads each row in the union of the two
// span-chunk intersections exactly once; accumulates into both head and tail
// partial sums, scales by 1/count, and atomically adds into d_out.
// block: 192 threads (one float4 column of H per thread).
__global__ void __launch_bounds__(H4_)
entity_accum_kernel(const float4* __restrict__ seq4,
                    const int* __restrict__ pos,
                    float* __restrict__ out) {
    const int c = blockIdx.x;
    const int b = blockIdx.y;

    int hs, he, ts, te;
    span_bounds(pos, b, 0, hs, he);
    span_bounds(pos, b, 1, ts, te);

    const int clo = c * CHUNK_ROWS;
    const int chi = clo + CHUNK_ROWS - 1;

    const int hlo = max(hs, clo), hhi = min(he, chi);
    const int tlo = max(ts, clo), thi = min(te, chi);
    const bool doH = hlo <= hhi;
    const bool doT = tlo <= thi;
    if (!doH && !doT) return;

    // Iterate union range within this chunk (gaps skipped via predicates).
    int lo, hi;
    if (doH && doT) { lo = min(hlo, tlo); hi = max(hhi, thi); }
    else if (doH)   { lo = hlo; hi = hhi; }
    else            { lo = tlo; hi = thi; }

    const int t = threadIdx.x;  // 0..191
    const float4* base = seq4 + (size_t)b * L_ * H4_ + t;

    float4 aH = make_float4(0.f, 0.f, 0.f, 0.f);
    float4 aT = make_float4(0.f, 0.f, 0.f, 0.f);

    #pragma unroll 4
    for (int r = lo; r <= hi; ++r) {
        const bool inH = (r >= hlo) & (r <= hhi);
        const bool inT = (r >= tlo) & (r <= thi);
        if (!(inH | inT)) continue;
        float4 v = __ldg(base + (size_t)r * H4_);
        if (inH) { aH.x += v.x; aH.y += v.y; aH.z += v.z; aH.w += v.w; }
        if (inT) { aT.x += v.x; aT.y += v.y; aT.z += v.z; aT.w += v.w; }
    }

    if (doH) {
        const float inv = 1.0f / (float)(he - hs + 1);
        float* o = out + (size_t)b * H_ + (size_t)t * 4;      // head = output slab 0
        atomicAdd(o + 0, aH.x * inv);
        atomicAdd(o + 1, aH.y * inv);
        atomicAdd(o + 2, aH.z * inv);
        atomicAdd(o + 3, aH.w * inv);
    }
    if (doT) {
        const float inv = 1.0f / (float)(te - ts + 1);
        float* o = out + (size_t)(B_ + b) * H_ + (size_t)t * 4;  // tail = slab 1
        atomicAdd(o + 0, aT.x * inv);
        atomicAdd(o + 1, aT.y * inv);
        atomicAdd(o + 2, aT.z * inv);
        atomicAdd(o + 3, aT.w * inv);
    }
}

extern "C" void kernel_launch(void* const* d_in, const int* in_sizes, int n_in,
                              void* d_out, int out_size) {
    const float4* seq4 = (const float4*)d_in[0];   // [B, L, H] fp32
    const int*    pos  = (const int*)d_in[1];      // [B, 4] int32
    float* out = (float*)d_out;                     // [2, B, H] fp32

    // Zero the accumulation target (d_out is poisoned before timing).
    cudaMemsetAsync(d_out, 0, (size_t)2 * B_ * H_ * sizeof(float));

    dim3 grid(NCHUNKS, B_);
    entity_accum_kernel<<<grid, H4_>>>(seq4, pos, out);
}